// round 4
// baseline (speedup 1.0000x reference)
#include <cuda_runtime.h>
#include <cuda_bf16.h>
#include <cstdint>

#define Nn 8192
#define IN_F 256
#define OUT_F 128
#define ALPHA 0.2f
#define SPLIT 2
#define JHALF (Nn / SPLIT) /* 4096 */
#define BK 64
#define NST (JHALF / BK)   /* 64 stages */

#define STRIDE 72          /* bf16 elems per row (64 data + 8 pad) */
#define STRIDE_B (STRIDE * 2) /* 144 bytes */
#define TILE_B (128 * STRIDE_B)   /* 18432 B per tile */
#define STAGE_B (4 * TILE_B)      /* Phi,Plo,Bhi,Blo = 73728 B */

// ---------------- scratch (device globals; no allocation allowed) ------------
__device__ float g_f1[Nn];
__device__ float g_f2[Nn];
__device__ float g_f2max;
__device__ float g_e2p[Nn];                      // exp(f2 - f2max)
__device__ float g_e2n[Nn];                      // exp(ALPHA*(f2 - f2max))
__device__ __nv_bfloat16 g_WhT_hi[OUT_F * Nn];   // transposed [feat][row]
__device__ __nv_bfloat16 g_WhT_lo[OUT_F * Nn];
__device__ float g_np0[Nn * OUT_F];              // partial numerators
__device__ float g_np1[Nn * OUT_F];
__device__ float g_lp0[Nn];                      // partial row sums
__device__ float g_lp1[Nn];

// ---------------- helpers ----------------------------------------------------
__device__ __forceinline__ uint32_t smem_to_u32(const void* p) {
    uint32_t a;
    asm("{ .reg .u64 t; cvta.to.shared.u64 t, %1; cvt.u32.u64 %0, t; }" : "=r"(a) : "l"(p));
    return a;
}

__device__ __forceinline__ void ldsm4(uint32_t* r, uint32_t addr) {
    asm volatile("ldmatrix.sync.aligned.m8n8.x4.shared.b16 {%0,%1,%2,%3}, [%4];"
                 : "=r"(r[0]), "=r"(r[1]), "=r"(r[2]), "=r"(r[3]) : "r"(addr));
}

__device__ __forceinline__ void mma16816(float* d, const uint32_t* a, uint32_t b0, uint32_t b1) {
    asm volatile("mma.sync.aligned.m16n8k16.row.col.f32.bf16.bf16.f32 "
                 "{%0,%1,%2,%3},{%4,%5,%6,%7},{%8,%9},{%0,%1,%2,%3};"
                 : "+f"(d[0]), "+f"(d[1]), "+f"(d[2]), "+f"(d[3])
                 : "r"(a[0]), "r"(a[1]), "r"(a[2]), "r"(a[3]), "r"(b0), "r"(b1));
}

#define CPASYNC16(dst, src) \
    asm volatile("cp.async.cg.shared.global [%0], [%1], 16;" :: "r"(dst), "l"(src))
#define CP_COMMIT() asm volatile("cp.async.commit_group;")
#define CP_WAIT0()  asm volatile("cp.async.wait_group 0;" ::: "memory")

// ---------------------------------------------------------------------------
// Kernel 1: tiled GEMM  Wh = h@W ; emits g_f1, g_f2, transposed bf16 hi/lo WhT.
// ---------------------------------------------------------------------------
__global__ __launch_bounds__(256) void k_proj(const float* __restrict__ h,
                                              const float* __restrict__ W,
                                              const float* __restrict__ a) {
    __shared__ float w_s[32 * 128];
    __shared__ float h_s[32 * 33];
    const int tid = threadIdx.x;
    const int i0 = blockIdx.x * 32;
    const int row = tid >> 3;
    const int f0 = (tid & 7) * 16;
    float acc[16];
#pragma unroll
    for (int j = 0; j < 16; j++) acc[j] = 0.f;

    for (int kc = 0; kc < IN_F; kc += 32) {
        __syncthreads();
        const float4* wsrc = (const float4*)(W + kc * OUT_F);
#pragma unroll
        for (int u = 0; u < 4; u++) ((float4*)w_s)[tid + u * 256] = wsrc[tid + u * 256];
        {
            const int kk = (tid & 7) * 4;
            float4 hv = *(const float4*)(h + (size_t)(i0 + row) * IN_F + kc + kk);
            h_s[row * 33 + kk + 0] = hv.x;
            h_s[row * 33 + kk + 1] = hv.y;
            h_s[row * 33 + kk + 2] = hv.z;
            h_s[row * 33 + kk + 3] = hv.w;
        }
        __syncthreads();
#pragma unroll
        for (int kk = 0; kk < 32; kk++) {
            const float hval = h_s[row * 33 + kk];
            const float* wrow = w_s + kk * 128 + f0;
#pragma unroll
            for (int j = 0; j < 16; j++) acc[j] = fmaf(hval, wrow[j], acc[j]);
        }
    }

    float s1 = 0.f, s2 = 0.f;
#pragma unroll
    for (int j = 0; j < 16; j++) {
        s1 = fmaf(acc[j], __ldg(&a[f0 + j]), s1);
        s2 = fmaf(acc[j], __ldg(&a[OUT_F + f0 + j]), s2);
    }
#pragma unroll
    for (int o = 1; o < 8; o <<= 1) {
        s1 += __shfl_xor_sync(0xFFFFFFFFu, s1, o);
        s2 += __shfl_xor_sync(0xFFFFFFFFu, s2, o);
    }
    if ((tid & 7) == 0) { g_f1[i0 + row] = s1; g_f2[i0 + row] = s2; }

    __syncthreads();
#pragma unroll
    for (int j = 0; j < 16; j++) w_s[row * 128 + f0 + j] = acc[j];
    __syncthreads();

    const int f = tid & 127;
    const int arr = tid >> 7;   // 0 = hi, 1 = lo
    uint32_t pk[16];
#pragma unroll
    for (int rp = 0; rp < 16; rp++) {
        float v0 = w_s[(2 * rp) * 128 + f];
        float v1 = w_s[(2 * rp + 1) * 128 + f];
        __nv_bfloat16 b0, b1;
        if (arr == 0) {
            b0 = __float2bfloat16_rn(v0);
            b1 = __float2bfloat16_rn(v1);
        } else {
            __nv_bfloat16 t0 = __float2bfloat16_rn(v0), t1 = __float2bfloat16_rn(v1);
            b0 = __float2bfloat16_rn(v0 - __bfloat162float(t0));
            b1 = __float2bfloat16_rn(v1 - __bfloat162float(t1));
        }
        pk[rp] = ((uint32_t)__bfloat16_as_ushort(b1) << 16) | (uint32_t)__bfloat16_as_ushort(b0);
    }
    __nv_bfloat16* dst = (arr == 0 ? g_WhT_hi : g_WhT_lo) + (size_t)f * Nn + i0;
#pragma unroll
    for (int q = 0; q < 4; q++)
        ((uint4*)dst)[q] = make_uint4(pk[4 * q], pk[4 * q + 1], pk[4 * q + 2], pk[4 * q + 3]);
}

// ---------------------------------------------------------------------------
// Kernel 2: global max of f2
// ---------------------------------------------------------------------------
__global__ __launch_bounds__(256) void k_f2max() {
    __shared__ float red[256];
    float m = -3.4e38f;
    for (int i = threadIdx.x; i < Nn; i += 256) m = fmaxf(m, g_f2[i]);
    red[threadIdx.x] = m;
    __syncthreads();
#pragma unroll
    for (int s = 128; s; s >>= 1) {
        if (threadIdx.x < s) red[threadIdx.x] = fmaxf(red[threadIdx.x], red[threadIdx.x + s]);
        __syncthreads();
    }
    if (threadIdx.x == 0) g_f2max = red[0];
}

// ---------------------------------------------------------------------------
// Kernel 2b: column exp tables (factorized softmax)
// ---------------------------------------------------------------------------
__global__ __launch_bounds__(256) void k_pre() {
    const int j = blockIdx.x * 256 + threadIdx.x;
    const float d = g_f2[j] - g_f2max;
    g_e2p[j] = expf(d);
    g_e2n[j] = expf(ALPHA * d);
}

// ---------------------------------------------------------------------------
// Kernel 3: fused masked-softmax + HMMA PV GEMM (bf16 hi/lo, fp32 accum).
// Inner loop has NO exp: p = (f1+f2>0 ? c_p*E2p_j : c_n*E2n_j) masked by adj.
// ---------------------------------------------------------------------------
#define SMEM_ATTN (2 * STAGE_B + 1024)

__global__ __launch_bounds__(512, 1) void k_attn(const int* __restrict__ adj) {
    extern __shared__ char smem_raw[];
    const uint32_t raw_u32 = smem_to_u32(smem_raw);
    const uint32_t base_u32 = (raw_u32 + 127u) & ~127u;
    char* base = smem_raw + (base_u32 - raw_u32);
    float* l_s = (float*)(base + 2 * STAGE_B);

    const int tid = threadIdx.x;
    const int rb = blockIdx.x >> 1;
    const int half = blockIdx.x & 1;
    const int i0 = rb * 128;
    const int jh = half * JHALF;

    // phase-A mapping: 4 threads per row, 16 cols each
    const int arow = tid >> 2;
    const int acol0 = (tid & 3) * 16;
    const size_t adjrow = (size_t)(i0 + arow) * Nn;
    const float f1v = g_f1[i0 + arow];
    const float f2m = g_f2max;
    const float bound = f1v + f2m;
    const float m_i = (bound > 0.f) ? bound : ALPHA * bound;
    // row constants (all results <= 1; continuous at branch point)
    const float c_p = __expf(bound - m_i);          // = 1 when bound > 0
    const float c_n = __expf(ALPHA * bound - m_i);  // = 1 when bound <= 0
    float lsum = 0.f;

    // warp mapping for MMA: 4x4 warps, tile 32x32
    const int wid = tid >> 5, lane = tid & 31;
    const int wm = wid >> 2, wn = wid & 3;
    float acc[2][4][4];
#pragma unroll
    for (int mt = 0; mt < 2; mt++)
#pragma unroll
        for (int nt = 0; nt < 4; nt++)
#pragma unroll
            for (int q = 0; q < 4; q++) acc[mt][nt][q] = 0.f;

    const uint32_t a_row = wm * 32 + (lane & 15);
    const uint32_t a_kofs = ((lane >> 4) << 3) * 2;
    const uint32_t b_n = wn * 32 + (lane & 7) + ((lane >> 4) & 1) * 8;
    const uint32_t b_kofs = (((lane >> 3) & 1) << 3) * 2;

    // preload stage 0 adj
    int4 av[4];
#pragma unroll
    for (int c = 0; c < 4; c++)
        av[c] = *(const int4*)(adj + adjrow + jh + acol0 + c * 4);

    for (int s = 0; s < NST; s++) {
        const int b = s & 1;
        const uint32_t buf = base_u32 + b * STAGE_B;
        const uint32_t phi = buf;
        const uint32_t plo = buf + TILE_B;
        const uint32_t bhi = buf + 2 * TILE_B;
        const uint32_t blo = buf + 3 * TILE_B;
        const int j0 = jh + s * BK;

        // ---- B tiles via cp.async ----
#pragma unroll
        for (int q = 0; q < 2; q++) {
            const int u = tid + q * 512;
            const int f = u >> 3, up = u & 7;
            const uint32_t doff = (uint32_t)f * STRIDE_B + up * 16;
            CPASYNC16(bhi + doff, g_WhT_hi + (size_t)f * Nn + j0 + up * 8);
            CPASYNC16(blo + doff, g_WhT_lo + (size_t)f * Nn + j0 + up * 8);
        }
        CP_COMMIT();

        // ---- P tile: table-driven softmax numerator -> bf16 hi/lo ----
#pragma unroll
        for (int c = 0; c < 4; c++) {
            const int col = acol0 + c * 4;
            const float4 fv = *(const float4*)(g_f2 + j0 + col);
            const float4 ep = *(const float4*)(g_e2p + j0 + col);
            const float4 en = *(const float4*)(g_e2n + j0 + col);
            float p0 = (av[c].x > 0) ? ((f1v + fv.x > 0.f) ? c_p * ep.x : c_n * en.x) : 0.f;
            float p1 = (av[c].y > 0) ? ((f1v + fv.y > 0.f) ? c_p * ep.y : c_n * en.y) : 0.f;
            float p2 = (av[c].z > 0) ? ((f1v + fv.z > 0.f) ? c_p * ep.z : c_n * en.z) : 0.f;
            float p3 = (av[c].w > 0) ? ((f1v + fv.w > 0.f) ? c_p * ep.w : c_n * en.w) : 0.f;
            lsum += (p0 + p1) + (p2 + p3);

            __nv_bfloat16 h0 = __float2bfloat16_rn(p0), h1 = __float2bfloat16_rn(p1);
            __nv_bfloat16 h2 = __float2bfloat16_rn(p2), h3 = __float2bfloat16_rn(p3);
            uint32_t hi01 = ((uint32_t)__bfloat16_as_ushort(h1) << 16) | __bfloat16_as_ushort(h0);
            uint32_t hi23 = ((uint32_t)__bfloat16_as_ushort(h3) << 16) | __bfloat16_as_ushort(h2);
            __nv_bfloat16 q0 = __float2bfloat16_rn(p0 - __bfloat162float(h0));
            __nv_bfloat16 q1 = __float2bfloat16_rn(p1 - __bfloat162float(h1));
            __nv_bfloat16 q2 = __float2bfloat16_rn(p2 - __bfloat162float(h2));
            __nv_bfloat16 q3 = __float2bfloat16_rn(p3 - __bfloat162float(h3));
            uint32_t lo01 = ((uint32_t)__bfloat16_as_ushort(q1) << 16) | __bfloat16_as_ushort(q0);
            uint32_t lo23 = ((uint32_t)__bfloat16_as_ushort(q3) << 16) | __bfloat16_as_ushort(q2);

            const uint32_t off = (uint32_t)arow * STRIDE_B + col * 2;
            *(uint2*)(base + (b * STAGE_B) + off) = make_uint2(hi01, hi23);
            *(uint2*)(base + (b * STAGE_B) + TILE_B + off) = make_uint2(lo01, lo23);
        }

        // ---- prefetch next-stage adj (DRAM latency hides under MMA) ----
        if (s + 1 < NST) {
            const int jn = j0 + BK;
#pragma unroll
            for (int c = 0; c < 4; c++)
                av[c] = *(const int4*)(adj + adjrow + jn + acol0 + c * 4);
        }

        CP_WAIT0();
        __syncthreads();

        // ---- MMA from buf b ----
#pragma unroll
        for (int ks = 0; ks < 4; ks++) {
            const uint32_t akb = (uint32_t)(ks * 16) * 2 + a_kofs;
            const uint32_t bkb = (uint32_t)(ks * 16) * 2 + b_kofs;
            uint32_t Ah[2][4], Al[2][4], Bh[2][4], Bl[2][4];
            ldsm4(Ah[0], phi + a_row * STRIDE_B + akb);
            ldsm4(Ah[1], phi + (a_row + 16) * STRIDE_B + akb);
            ldsm4(Al[0], plo + a_row * STRIDE_B + akb);
            ldsm4(Al[1], plo + (a_row + 16) * STRIDE_B + akb);
            ldsm4(Bh[0], bhi + b_n * STRIDE_B + bkb);
            ldsm4(Bh[1], bhi + (b_n + 16) * STRIDE_B + bkb);
            ldsm4(Bl[0], blo + b_n * STRIDE_B + bkb);
            ldsm4(Bl[1], blo + (b_n + 16) * STRIDE_B + bkb);
#pragma unroll
            for (int mt = 0; mt < 2; mt++) {
#pragma unroll
                for (int n16 = 0; n16 < 2; n16++) {
#pragma unroll
                    for (int hh = 0; hh < 2; hh++) {
                        const int nt = n16 * 2 + hh;
                        const uint32_t bh0 = Bh[n16][hh * 2], bh1 = Bh[n16][hh * 2 + 1];
                        const uint32_t bl0 = Bl[n16][hh * 2], bl1 = Bl[n16][hh * 2 + 1];
                        mma16816(acc[mt][nt], Ah[mt], bh0, bh1);
                        mma16816(acc[mt][nt], Ah[mt], bl0, bl1);
                        mma16816(acc[mt][nt], Al[mt], bh0, bh1);
                    }
                }
            }
        }
    }

    // ---- row-sum reduction (4 threads/row) ----
#pragma unroll
    for (int o = 1; o < 4; o <<= 1) lsum += __shfl_xor_sync(0xFFFFFFFFu, lsum, o);
    if ((tid & 3) == 0) l_s[arow] = lsum;
    __syncthreads();
    if (tid < 128) (half ? g_lp1 : g_lp0)[i0 + tid] = l_s[tid];

    // ---- write partial numerators ----
    float* np = (half ? g_np1 : g_np0);
#pragma unroll
    for (int mt = 0; mt < 2; mt++) {
#pragma unroll
        for (int nt = 0; nt < 4; nt++) {
            const int r0 = i0 + wm * 32 + mt * 16 + (lane >> 2);
            const int cc = wn * 32 + nt * 8 + (lane & 3) * 2;
            *(float2*)(np + (size_t)r0 * OUT_F + cc) = make_float2(acc[mt][nt][0], acc[mt][nt][1]);
            *(float2*)(np + (size_t)(r0 + 8) * OUT_F + cc) = make_float2(acc[mt][nt][2], acc[mt][nt][3]);
        }
    }
}

// ---------------------------------------------------------------------------
// Kernel 4: combine halves, normalize
// ---------------------------------------------------------------------------
__global__ __launch_bounds__(256) void k_norm(float* __restrict__ out) {
    const int idx = blockIdx.x * 256 + threadIdx.x;  // float4 index
    const int i = idx >> 5;                          // row
    const float inv = 1.f / (g_lp0[i] + g_lp1[i]);
    const float4 x = ((const float4*)g_np0)[idx];
    const float4 y = ((const float4*)g_np1)[idx];
    ((float4*)out)[idx] = make_float4((x.x + y.x) * inv, (x.y + y.y) * inv,
                                      (x.z + y.z) * inv, (x.w + y.w) * inv);
}

// ---------------------------------------------------------------------------
extern "C" void kernel_launch(void* const* d_in, const int* in_sizes, int n_in,
                              void* d_out, int out_size) {
    const float* h   = (const float*)d_in[0];
    const int*   adj = (const int*)d_in[1];
    const float* W   = (const float*)d_in[2];
    const float* a   = (const float*)d_in[3];
    float* out = (float*)d_out;

    static int smem_set = 0;
    if (!smem_set) {
        cudaFuncSetAttribute(k_attn, cudaFuncAttributeMaxDynamicSharedMemorySize, SMEM_ATTN);
        smem_set = 1;
    }

    k_proj<<<Nn / 32, 256>>>(h, W, a);
    k_f2max<<<1, 256>>>();
    k_pre<<<Nn / 256, 256>>>();
    k_attn<<<(Nn / 128) * SPLIT, 512, SMEM_ATTN>>>(adj);
    k_norm<<<Nn * OUT_F / 4 / 256, 256>>>(out);
}

// round 5
// speedup vs baseline: 1.0172x; 1.0172x over previous
#include <cuda_runtime.h>
#include <cuda_bf16.h>
#include <cstdint>

#define Nn 8192
#define IN_F 256
#define OUT_F 128
#define ALPHA 0.2f
#define SPLIT 2
#define JHALF (Nn / SPLIT) /* 4096 */
#define BK 64
#define NST (JHALF / BK)   /* 64 stages */

#define STRIDE_B 144              /* bytes per feat row: 64 bf16 + 8 pad */
#define TILE_B (128 * STRIDE_B)   /* 18432 B per tile */
#define BUF_B (2 * TILE_B)        /* hi+lo per stage buffer = 36864 B */
#define SMEM_ATTN (2 * BUF_B + 256)

// ---------------- scratch (device globals; no allocation allowed) ------------
__device__ float g_f1[Nn];
__device__ float g_f2[Nn];
__device__ float g_f2pmax[256];
__device__ float4 g_tab[Nn];     // (f2, exp(f2-fm), exp(a*(f2-fm)), 0)
__device__ float4 g_rowc[Nn];    // (f1, cp, cn, 0)
__device__ __nv_bfloat16 g_WhT_hi[OUT_F * Nn];   // transposed [feat][row]
__device__ __nv_bfloat16 g_WhT_lo[OUT_F * Nn];
__device__ float g_np0[Nn * OUT_F];              // partial numerators
__device__ float g_np1[Nn * OUT_F];
__device__ float g_lp0[Nn];                      // partial row sums
__device__ float g_lp1[Nn];

// ---------------- helpers ----------------------------------------------------
__device__ __forceinline__ uint32_t smem_to_u32(const void* p) {
    uint32_t a;
    asm("{ .reg .u64 t; cvta.to.shared.u64 t, %1; cvt.u32.u64 %0, t; }" : "=r"(a) : "l"(p));
    return a;
}

__device__ __forceinline__ void ldsm4(uint32_t* r, uint32_t addr) {
    asm volatile("ldmatrix.sync.aligned.m8n8.x4.shared.b16 {%0,%1,%2,%3}, [%4];"
                 : "=r"(r[0]), "=r"(r[1]), "=r"(r[2]), "=r"(r[3]) : "r"(addr));
}

__device__ __forceinline__ void mma16816(float* d, const uint32_t* a, uint32_t b0, uint32_t b1) {
    asm volatile("mma.sync.aligned.m16n8k16.row.col.f32.bf16.bf16.f32 "
                 "{%0,%1,%2,%3},{%4,%5,%6,%7},{%8,%9},{%0,%1,%2,%3};"
                 : "+f"(d[0]), "+f"(d[1]), "+f"(d[2]), "+f"(d[3])
                 : "r"(a[0]), "r"(a[1]), "r"(a[2]), "r"(a[3]), "r"(b0), "r"(b1));
}

#define CPASYNC16(dst, src) \
    asm volatile("cp.async.cg.shared.global [%0], [%1], 16;" :: "r"(dst), "l"(src))
#define CP_COMMIT() asm volatile("cp.async.commit_group;")
#define CP_WAIT1()  asm volatile("cp.async.wait_group 1;" ::: "memory")

// P-element producer: computes masked softmax numerators for 2 adjacent cols,
// packs bf16 hi + exact lo residual (bit-extracted, Sterbenz-exact subtraction)
__device__ __forceinline__ void produce(int2 a, float4 t0, float4 t1, float4 rc,
                                        float& lsum, uint32_t& hi, uint32_t& lo) {
    const float s0 = rc.x + t0.x;
    const float s1 = rc.x + t1.x;
    float p0 = (s0 > 0.f) ? rc.y * t0.y : rc.z * t0.z;
    float p1 = (s1 > 0.f) ? rc.y * t1.y : rc.z * t1.z;
    p0 = (a.x > 0) ? p0 : 0.f;
    p1 = (a.y > 0) ? p1 : 0.f;
    lsum += p0 + p1;
    uint32_t h;
    asm("cvt.rn.bf16x2.f32 %0, %1, %2;" : "=r"(h) : "f"(p1), "f"(p0));
    const float h0 = __uint_as_float(h << 16);
    const float h1 = __uint_as_float(h & 0xFFFF0000u);
    asm("cvt.rn.bf16x2.f32 %0, %1, %2;" : "=r"(lo) : "f"(p1 - h1), "f"(p0 - h0));
    hi = h;
}

// ---------------------------------------------------------------------------
// Kernel 1: Wh = h@W (conflict-free tiling); emits f1/f2, per-block f2 max,
// and transposed bf16 hi/lo WhT. Grid 256 x 256 thr, 32 rows/block.
// ---------------------------------------------------------------------------
__global__ __launch_bounds__(256) void k_proj(const float* __restrict__ h,
                                              const float* __restrict__ W,
                                              const float* __restrict__ a) {
    __shared__ float w_s[32 * 128];
    __shared__ float h_s[32 * 33];
    __shared__ float red[32];
    const int tid = threadIdx.x;
    const int i0 = blockIdx.x * 32;
    const int row = tid >> 3;
    const int c8 = tid & 7;      // cols: c8*4 + j4*32 .. +3
    float4 acc[4];
#pragma unroll
    for (int j4 = 0; j4 < 4; j4++) acc[j4] = make_float4(0.f, 0.f, 0.f, 0.f);

    for (int kc = 0; kc < IN_F; kc += 32) {
        __syncthreads();
        const float4* wsrc = (const float4*)(W + kc * OUT_F);
#pragma unroll
        for (int u = 0; u < 4; u++) ((float4*)w_s)[tid + u * 256] = wsrc[tid + u * 256];
        {
            float4 hv = *(const float4*)(h + (size_t)(i0 + row) * IN_F + kc + c8 * 4);
            h_s[row * 33 + c8 * 4 + 0] = hv.x;
            h_s[row * 33 + c8 * 4 + 1] = hv.y;
            h_s[row * 33 + c8 * 4 + 2] = hv.z;
            h_s[row * 33 + c8 * 4 + 3] = hv.w;
        }
        __syncthreads();
#pragma unroll
        for (int kk = 0; kk < 32; kk++) {
            const float hval = h_s[row * 33 + kk];
            const float4* wr = ((const float4*)w_s) + kk * 32 + c8;
#pragma unroll
            for (int j4 = 0; j4 < 4; j4++) {
                const float4 wv = wr[j4 * 8];
                acc[j4].x = fmaf(hval, wv.x, acc[j4].x);
                acc[j4].y = fmaf(hval, wv.y, acc[j4].y);
                acc[j4].z = fmaf(hval, wv.z, acc[j4].z);
                acc[j4].w = fmaf(hval, wv.w, acc[j4].w);
            }
        }
    }

    // f1 / f2 per row (8 threads per row)
    float s1 = 0.f, s2 = 0.f;
#pragma unroll
    for (int j4 = 0; j4 < 4; j4++) {
        const float4 a1v = *(const float4*)(a + c8 * 4 + j4 * 32);
        const float4 a2v = *(const float4*)(a + OUT_F + c8 * 4 + j4 * 32);
        s1 += acc[j4].x * a1v.x + acc[j4].y * a1v.y + acc[j4].z * a1v.z + acc[j4].w * a1v.w;
        s2 += acc[j4].x * a2v.x + acc[j4].y * a2v.y + acc[j4].z * a2v.z + acc[j4].w * a2v.w;
    }
#pragma unroll
    for (int o = 1; o < 8; o <<= 1) {
        s1 += __shfl_xor_sync(0xFFFFFFFFu, s1, o);
        s2 += __shfl_xor_sync(0xFFFFFFFFu, s2, o);
    }
    if (c8 == 0) { g_f1[i0 + row] = s1; g_f2[i0 + row] = s2; red[row] = s2; }
    __syncthreads();
    if (tid < 32) {
        float m = red[tid];
#pragma unroll
        for (int o = 16; o; o >>= 1) m = fmaxf(m, __shfl_xor_sync(0xFFFFFFFFu, m, o));
        if (tid == 0) g_f2pmax[blockIdx.x] = m;
    }

    // stage Wh into w_s (barrier above protects), then transposed hi/lo write
#pragma unroll
    for (int j4 = 0; j4 < 4; j4++)
        ((float4*)w_s)[row * 32 + c8 + j4 * 8] = acc[j4];
    __syncthreads();

    const int f = tid & 127;
    const int arr = tid >> 7;   // 0 = hi, 1 = lo
    uint32_t pk[16];
#pragma unroll
    for (int rp = 0; rp < 16; rp++) {
        float v0 = w_s[(2 * rp) * 128 + f];
        float v1 = w_s[(2 * rp + 1) * 128 + f];
        __nv_bfloat16 b0, b1;
        if (arr == 0) {
            b0 = __float2bfloat16_rn(v0);
            b1 = __float2bfloat16_rn(v1);
        } else {
            __nv_bfloat16 t0 = __float2bfloat16_rn(v0), t1 = __float2bfloat16_rn(v1);
            b0 = __float2bfloat16_rn(v0 - __bfloat162float(t0));
            b1 = __float2bfloat16_rn(v1 - __bfloat162float(t1));
        }
        pk[rp] = ((uint32_t)__bfloat16_as_ushort(b1) << 16) | (uint32_t)__bfloat16_as_ushort(b0);
    }
    __nv_bfloat16* dst = (arr == 0 ? g_WhT_hi : g_WhT_lo) + (size_t)f * Nn + i0;
#pragma unroll
    for (int q = 0; q < 4; q++)
        ((uint4*)dst)[q] = make_uint4(pk[4 * q], pk[4 * q + 1], pk[4 * q + 2], pk[4 * q + 3]);
}

// ---------------------------------------------------------------------------
// Kernel 2: finish f2max reduction + build col/row tables. Grid 32 x 256.
// ---------------------------------------------------------------------------
__global__ __launch_bounds__(256) void k_pre() {
    __shared__ float red[256];
    const int t = threadIdx.x;
    red[t] = g_f2pmax[t];
    __syncthreads();
#pragma unroll
    for (int s = 128; s; s >>= 1) {
        if (t < s) red[t] = fmaxf(red[t], red[t + s]);
        __syncthreads();
    }
    const float fm = red[0];
    const int j = blockIdx.x * 256 + t;
    const float f2 = g_f2[j];
    const float d = f2 - fm;
    g_tab[j] = make_float4(f2, expf(d), expf(ALPHA * d), 0.f);
    const float f1 = g_f1[j];
    const float bound = f1 + fm;
    const float m = bound > 0.f ? bound : ALPHA * bound;
    g_rowc[j] = make_float4(f1, expf(bound - m), expf(ALPHA * bound - m), 0.f);
}

// ---------------------------------------------------------------------------
// Kernel 3: fused masked-softmax + HMMA PV GEMM.
// P produced DIRECTLY in MMA A-fragment registers (no P smem, no A ldmatrix).
// 16 warps, grid 8x2 (warp tile 16 rows x 64 cols). B double-buffered cp.async.
// ---------------------------------------------------------------------------
__global__ __launch_bounds__(512, 1) void k_attn(const int* __restrict__ adj) {
    extern __shared__ char smem_raw[];
    const uint32_t raw = smem_to_u32(smem_raw);
    const uint32_t base = (raw + 127u) & ~127u;

    const int tid = threadIdx.x;
    const int wid = tid >> 5, lane = tid & 31;
    const int wm = wid >> 1, wn = wid & 1;
    const int gr = lane >> 2, lx = lane & 3;
    const int rb = blockIdx.x >> 1, half = blockIdx.x & 1;
    const int i0 = rb * 128, jh = half * JHALF;

    const int r0 = i0 + wm * 16 + gr;
    const float4 rc0 = g_rowc[r0];
    const float4 rc1 = g_rowc[r0 + 8];
    const int2* arow0 = (const int2*)(adj + (size_t)r0 * Nn);
    const int2* arow1 = (const int2*)(adj + (size_t)(r0 + 8) * Nn);

    float acc[8][4];
#pragma unroll
    for (int nt = 0; nt < 8; nt++)
#pragma unroll
        for (int q = 0; q < 4; q++) acc[nt][q] = 0.f;
    float lsum0 = 0.f, lsum1 = 0.f;

    // fill stage 0 B tiles
    {
        const uint32_t bhi = base, blo = base + TILE_B;
#pragma unroll
        for (int q = 0; q < 2; q++) {
            const int u = tid + q * 512;
            const int f = u >> 3, up = u & 7;
            const uint32_t doff = (uint32_t)f * STRIDE_B + up * 16;
            CPASYNC16(bhi + doff, g_WhT_hi + (size_t)f * Nn + jh + up * 8);
            CPASYNC16(blo + doff, g_WhT_lo + (size_t)f * Nn + jh + up * 8);
        }
        CP_COMMIT();
    }

    // adj prefetch for (s=0, ks=0): [delta][colgroup]
    int2 an00, an01, an10, an11;
    {
        const int ci = (jh + lx * 2) >> 1;
        an00 = arow0[ci]; an01 = arow0[ci + 4];
        an10 = arow1[ci]; an11 = arow1[ci + 4];
    }

    // B ldsm lane addressing (constant across stages)
    const uint32_t lrow = (uint32_t)(wn * 64 + (lane & 7) + ((lane >> 4) & 1) * 8);
    const uint32_t kbl = ((lane >> 3) & 1) * 16;

    for (int s = 0; s < NST; s++) {
        const uint32_t bhi = base + (s & 1) * BUF_B;
        const uint32_t blo = bhi + TILE_B;
        const int j0 = jh + s * BK;

        __syncthreads();   // everyone done reading the other buffer
        if (s + 1 < NST) {
            const uint32_t nhi = base + ((s + 1) & 1) * BUF_B;
            const uint32_t nlo = nhi + TILE_B;
            const int jn = j0 + BK;
#pragma unroll
            for (int q = 0; q < 2; q++) {
                const int u = tid + q * 512;
                const int f = u >> 3, up = u & 7;
                const uint32_t doff = (uint32_t)f * STRIDE_B + up * 16;
                CPASYNC16(nhi + doff, g_WhT_hi + (size_t)f * Nn + jn + up * 8);
                CPASYNC16(nlo + doff, g_WhT_lo + (size_t)f * Nn + jn + up * 8);
            }
        }
        CP_COMMIT();
        CP_WAIT1();        // current stage's fill complete (next stage in flight)
        __syncthreads();

#pragma unroll
        for (int ks = 0; ks < 4; ks++) {
            const int2 ac00 = an00, ac01 = an01, ac10 = an10, ac11 = an11;
            // prefetch next ks (or next stage's ks0)
            if (ks < 3) {
                const int ci = (j0 + (ks + 1) * 16 + lx * 2) >> 1;
                an00 = arow0[ci]; an01 = arow0[ci + 4];
                an10 = arow1[ci]; an11 = arow1[ci + 4];
            } else if (s + 1 < NST) {
                const int ci = (j0 + BK + lx * 2) >> 1;
                an00 = arow0[ci]; an01 = arow0[ci + 4];
                an10 = arow1[ci]; an11 = arow1[ci + 4];
            }

            const int jc = j0 + ks * 16 + lx * 2;
            const float4 ta0 = g_tab[jc],     ta1 = g_tab[jc + 1];
            const float4 tb0 = g_tab[jc + 8], tb1 = g_tab[jc + 9];

            // A fragments in registers: a0=(gr,klo) a1=(gr+8,klo) a2=(gr,khi) a3=(gr+8,khi)
            uint32_t Ah[4], Al[4];
            produce(ac00, ta0, ta1, rc0, lsum0, Ah[0], Al[0]);
            produce(ac10, ta0, ta1, rc1, lsum1, Ah[1], Al[1]);
            produce(ac01, tb0, tb1, rc0, lsum0, Ah[2], Al[2]);
            produce(ac11, tb0, tb1, rc1, lsum1, Ah[3], Al[3]);

            const uint32_t kb = kbl + (uint32_t)ks * 32;
#pragma unroll
            for (int grp = 0; grp < 4; grp++) {
                uint32_t bh[4], bl[4];
                const uint32_t ro = (lrow + grp * 16) * STRIDE_B + kb;
                ldsm4(bh, bhi + ro);
                ldsm4(bl, blo + ro);
#pragma unroll
                for (int hh = 0; hh < 2; hh++) {
                    const int nt = grp * 2 + hh;
                    mma16816(acc[nt], Ah, bh[hh * 2], bh[hh * 2 + 1]);
                    mma16816(acc[nt], Ah, bl[hh * 2], bl[hh * 2 + 1]);
                    mma16816(acc[nt], Al, bh[hh * 2], bh[hh * 2 + 1]);
                }
            }
        }
    }

    // row-sum reduce over the 4 lanes of each quad (cols partitioned by lx)
    lsum0 += __shfl_xor_sync(0xFFFFFFFFu, lsum0, 1);
    lsum0 += __shfl_xor_sync(0xFFFFFFFFu, lsum0, 2);
    lsum1 += __shfl_xor_sync(0xFFFFFFFFu, lsum1, 1);
    lsum1 += __shfl_xor_sync(0xFFFFFFFFu, lsum1, 2);
    if (wn == 0 && lx == 0) {
        float* lp = half ? g_lp1 : g_lp0;
        lp[r0] = lsum0;
        lp[r0 + 8] = lsum1;
    }

    // write partial numerators (c-frag: rows gr/gr+8, cols lx*2,+1 per n8 tile)
    float* np = half ? g_np1 : g_np0;
#pragma unroll
    for (int nt = 0; nt < 8; nt++) {
        const int col = wn * 64 + nt * 8 + lx * 2;
        *(float2*)(np + (size_t)r0 * OUT_F + col) = make_float2(acc[nt][0], acc[nt][1]);
        *(float2*)(np + (size_t)(r0 + 8) * OUT_F + col) = make_float2(acc[nt][2], acc[nt][3]);
    }
}

// ---------------------------------------------------------------------------
// Kernel 4: combine halves, normalize
// ---------------------------------------------------------------------------
__global__ __launch_bounds__(256) void k_norm(float* __restrict__ out) {
    const int idx = blockIdx.x * 256 + threadIdx.x;  // float4 index
    const int i = idx >> 5;                          // row
    const float inv = 1.f / (g_lp0[i] + g_lp1[i]);
    const float4 x = ((const float4*)g_np0)[idx];
    const float4 y = ((const float4*)g_np1)[idx];
    ((float4*)out)[idx] = make_float4((x.x + y.x) * inv, (x.y + y.y) * inv,
                                      (x.z + y.z) * inv, (x.w + y.w) * inv);
}

// ---------------------------------------------------------------------------
extern "C" void kernel_launch(void* const* d_in, const int* in_sizes, int n_in,
                              void* d_out, int out_size) {
    const float* h   = (const float*)d_in[0];
    const int*   adj = (const int*)d_in[1];
    const float* W   = (const float*)d_in[2];
    const float* a   = (const float*)d_in[3];
    float* out = (float*)d_out;

    static int smem_set = 0;
    if (!smem_set) {
        cudaFuncSetAttribute(k_attn, cudaFuncAttributeMaxDynamicSharedMemorySize, SMEM_ATTN);
        smem_set = 1;
    }

    k_proj<<<Nn / 32, 256>>>(h, W, a);
    k_pre<<<Nn / 256, 256>>>();
    k_attn<<<(Nn / 128) * SPLIT, 512, SMEM_ATTN>>>(adj);
    k_norm<<<Nn * OUT_F / 4 / 256, 256>>>(out);
}

// round 6
// speedup vs baseline: 1.2402x; 1.2193x over previous
#include <cuda_runtime.h>
#include <cuda_bf16.h>
#include <cstdint>

#define Nn 8192
#define IN_F 256
#define OUT_F 128
#define ALPHA 0.2f
#define SPLIT 2
#define JHALF (Nn / SPLIT) /* 4096 */
#define BK 64
#define NST (JHALF / BK)   /* 64 stages */

#define ROWSTRIDE_B 320            /* bytes per feat row in smem: 64 fp32 + 16 pad */
#define TILE_B (128 * ROWSTRIDE_B) /* 40960 B per stage buffer */
#define SMEM_ATTN (2 * TILE_B + 256)

// ---------------- scratch (device globals; no allocation allowed) ------------
__device__ float g_f1[Nn];
__device__ float g_f2[Nn];
__device__ float g_f2pmax[256];
__device__ float4 g_tab[Nn];     // (f2, exp(f2-fm), exp(a*(f2-fm)), 0)
__device__ float4 g_rowc[Nn];    // (f1, cp, cn, 0)
__device__ float g_WhT[OUT_F * Nn];   // transposed Wh, pre-rounded to tf32
__device__ float g_np0[Nn * OUT_F];   // partial numerators
__device__ float g_np1[Nn * OUT_F];
__device__ float g_lp0[Nn];           // partial row sums
__device__ float g_lp1[Nn];

// ---------------- helpers ----------------------------------------------------
__device__ __forceinline__ uint32_t smem_to_u32(const void* p) {
    uint32_t a;
    asm("{ .reg .u64 t; cvta.to.shared.u64 t, %1; cvt.u32.u64 %0, t; }" : "=r"(a) : "l"(p));
    return a;
}

__device__ __forceinline__ uint32_t f2tf32(float v) {
    uint32_t r;
    asm("cvt.rna.tf32.f32 %0, %1;" : "=r"(r) : "f"(v));
    return r;
}

__device__ __forceinline__ void mma_tf32(float* d, const uint32_t* a, uint32_t b0, uint32_t b1) {
    asm volatile("mma.sync.aligned.m16n8k8.row.col.f32.tf32.tf32.f32 "
                 "{%0,%1,%2,%3},{%4,%5,%6,%7},{%8,%9},{%0,%1,%2,%3};"
                 : "+f"(d[0]), "+f"(d[1]), "+f"(d[2]), "+f"(d[3])
                 : "r"(a[0]), "r"(a[1]), "r"(a[2]), "r"(a[3]), "r"(b0), "r"(b1));
}

#define LDS128(r, addr) \
    asm volatile("ld.shared.v4.b32 {%0,%1,%2,%3}, [%4];" \
                 : "=r"((r)[0]), "=r"((r)[1]), "=r"((r)[2]), "=r"((r)[3]) : "r"(addr))

#define CPASYNC16(dst, src) \
    asm volatile("cp.async.cg.shared.global [%0], [%1], 16;" :: "r"(dst), "l"(src))
#define CP_COMMIT() asm volatile("cp.async.commit_group;")
#define CP_WAIT1()  asm volatile("cp.async.wait_group 1;" ::: "memory")

// masked factorized-softmax numerator for one element
__device__ __forceinline__ float Pv(int a, float4 T, float thr, float cp, float cn, float& ls) {
    const float e = (T.x > thr) ? cp * T.y : cn * T.z;
    const float p = (a > 0) ? e : 0.f;
    ls += p;
    return p;
}

// ---------------------------------------------------------------------------
// Kernel 1: Wh = h@W ; emits f1/f2, per-block f2 max, and transposed tf32 WhT.
// ---------------------------------------------------------------------------
__global__ __launch_bounds__(256) void k_proj(const float* __restrict__ h,
                                              const float* __restrict__ W,
                                              const float* __restrict__ a) {
    __shared__ float w_s[32 * 128];
    __shared__ float h_s[32 * 33];
    __shared__ float red[32];
    const int tid = threadIdx.x;
    const int i0 = blockIdx.x * 32;
    const int row = tid >> 3;
    const int c8 = tid & 7;
    float4 acc[4];
#pragma unroll
    for (int j4 = 0; j4 < 4; j4++) acc[j4] = make_float4(0.f, 0.f, 0.f, 0.f);

    for (int kc = 0; kc < IN_F; kc += 32) {
        __syncthreads();
        const float4* wsrc = (const float4*)(W + kc * OUT_F);
#pragma unroll
        for (int u = 0; u < 4; u++) ((float4*)w_s)[tid + u * 256] = wsrc[tid + u * 256];
        {
            float4 hv = *(const float4*)(h + (size_t)(i0 + row) * IN_F + kc + c8 * 4);
            h_s[row * 33 + c8 * 4 + 0] = hv.x;
            h_s[row * 33 + c8 * 4 + 1] = hv.y;
            h_s[row * 33 + c8 * 4 + 2] = hv.z;
            h_s[row * 33 + c8 * 4 + 3] = hv.w;
        }
        __syncthreads();
#pragma unroll
        for (int kk = 0; kk < 32; kk++) {
            const float hval = h_s[row * 33 + kk];
            const float4* wr = ((const float4*)w_s) + kk * 32 + c8;
#pragma unroll
            for (int j4 = 0; j4 < 4; j4++) {
                const float4 wv = wr[j4 * 8];
                acc[j4].x = fmaf(hval, wv.x, acc[j4].x);
                acc[j4].y = fmaf(hval, wv.y, acc[j4].y);
                acc[j4].z = fmaf(hval, wv.z, acc[j4].z);
                acc[j4].w = fmaf(hval, wv.w, acc[j4].w);
            }
        }
    }

    // f1 / f2 per row (8 threads per row)
    float s1 = 0.f, s2 = 0.f;
#pragma unroll
    for (int j4 = 0; j4 < 4; j4++) {
        const float4 a1v = *(const float4*)(a + c8 * 4 + j4 * 32);
        const float4 a2v = *(const float4*)(a + OUT_F + c8 * 4 + j4 * 32);
        s1 += acc[j4].x * a1v.x + acc[j4].y * a1v.y + acc[j4].z * a1v.z + acc[j4].w * a1v.w;
        s2 += acc[j4].x * a2v.x + acc[j4].y * a2v.y + acc[j4].z * a2v.z + acc[j4].w * a2v.w;
    }
#pragma unroll
    for (int o = 1; o < 8; o <<= 1) {
        s1 += __shfl_xor_sync(0xFFFFFFFFu, s1, o);
        s2 += __shfl_xor_sync(0xFFFFFFFFu, s2, o);
    }
    if (c8 == 0) { g_f1[i0 + row] = s1; g_f2[i0 + row] = s2; red[row] = s2; }
    __syncthreads();
    if (tid < 32) {
        float m = red[tid];
#pragma unroll
        for (int o = 16; o; o >>= 1) m = fmaxf(m, __shfl_xor_sync(0xFFFFFFFFu, m, o));
        if (tid == 0) g_f2pmax[blockIdx.x] = m;
    }

    // stage Wh into w_s, then transposed tf32-rounded write
#pragma unroll
    for (int j4 = 0; j4 < 4; j4++)
        ((float4*)w_s)[row * 32 + c8 + j4 * 8] = acc[j4];
    __syncthreads();

    const int f = tid & 127;
    const int hb = tid >> 7;   // 0: rows 0-15, 1: rows 16-31
    uint32_t pk[16];
#pragma unroll
    for (int q = 0; q < 16; q++)
        pk[q] = f2tf32(w_s[(hb * 16 + q) * 128 + f]);
    uint4* dst = (uint4*)(g_WhT + (size_t)f * Nn + i0 + hb * 16);
#pragma unroll
    for (int q = 0; q < 4; q++)
        dst[q] = make_uint4(pk[4 * q], pk[4 * q + 1], pk[4 * q + 2], pk[4 * q + 3]);
}

// ---------------------------------------------------------------------------
// Kernel 2: finish f2max reduction + build col/row tables. Grid 32 x 256.
// ---------------------------------------------------------------------------
__global__ __launch_bounds__(256) void k_pre() {
    __shared__ float red[256];
    const int t = threadIdx.x;
    red[t] = g_f2pmax[t];
    __syncthreads();
#pragma unroll
    for (int s = 128; s; s >>= 1) {
        if (t < s) red[t] = fmaxf(red[t], red[t + s]);
        __syncthreads();
    }
    const float fm = red[0];
    const int j = blockIdx.x * 256 + t;
    const float f2 = g_f2[j];
    const float d = f2 - fm;
    g_tab[j] = make_float4(f2, expf(d), expf(ALPHA * d), 0.f);
    const float f1 = g_f1[j];
    const float bound = f1 + fm;
    const float m = bound > 0.f ? bound : ALPHA * bound;
    g_rowc[j] = make_float4(f1, expf(bound - m), expf(ALPHA * bound - m), 0.f);
}

// ---------------------------------------------------------------------------
// Kernel 3: fused masked-softmax + TF32 HMMA PV GEMM (single term).
// 16 warps (8x2). Warp tile 16 rows x 64 feats. k-slot<->column remap:
//   j = 4c + v + 16u  (c = lane&3, v = 0..3, u = 0..3)  => per (u, ntile) one
//   float4 LDS serves b0/b1 of two k8 MMAs; A/adj/table all 16B-vectorized.
// ---------------------------------------------------------------------------
__global__ __launch_bounds__(512, 1) void k_attn(const int* __restrict__ adj) {
    extern __shared__ char smem_raw[];
    const uint32_t raw = smem_to_u32(smem_raw);
    const uint32_t base = (raw + 127u) & ~127u;

    const int tid = threadIdx.x;
    const int wid = tid >> 5, lane = tid & 31;
    const int wm = wid >> 1, wn = wid & 1;
    const int nq = lane >> 2, c = lane & 3;
    const int rb = blockIdx.x >> 1, half = blockIdx.x & 1;
    const int i0 = rb * 128, jh = half * JHALF;

    const int r0 = i0 + wm * 16 + nq;
    const int r1 = r0 + 8;
    const float4 rc0 = g_rowc[r0];
    const float4 rc1 = g_rowc[r1];
    const float thr0 = -rc0.x, cp0 = rc0.y, cn0 = rc0.z;
    const float thr1 = -rc1.x, cp1 = rc1.y, cn1 = rc1.z;
    const int4* arow0 = (const int4*)(adj + (size_t)r0 * Nn);
    const int4* arow1 = (const int4*)(adj + (size_t)r1 * Nn);

    float acc[8][4];
#pragma unroll
    for (int nt = 0; nt < 8; nt++)
#pragma unroll
        for (int q = 0; q < 4; q++) acc[nt][q] = 0.f;
    float lsum0 = 0.f, lsum1 = 0.f;

    // B LDS base for this thread (nt adds 8*320, u adds 64, within a buffer)
    const uint32_t bline = (uint32_t)(wn * 64 + nq) * ROWSTRIDE_B + (uint32_t)c * 16;

    // ---- fill stage 0 ----
    {
        const uint32_t buf = base;
#pragma unroll
        for (int q = 0; q < 4; q++) {
            const int u16 = tid + q * 512;
            const int feat = u16 >> 4, ch = u16 & 15;
            CPASYNC16(buf + (uint32_t)feat * ROWSTRIDE_B + ch * 16,
                      g_WhT + (size_t)feat * Nn + jh + ch * 4);
        }
        CP_COMMIT();
    }

    // ---- prefetch (s=0, u=0) adj + tables ----
    int4 nA, nB;
    float4 nT0, nT1, nT2, nT3;
    {
        const int ch = (jh >> 2) + c;     // chunk index (float4/int4 granularity)
        nA = arow0[ch];
        nB = arow1[ch];
        const int jt = jh + 4 * c;
        nT0 = g_tab[jt]; nT1 = g_tab[jt + 1]; nT2 = g_tab[jt + 2]; nT3 = g_tab[jt + 3];
    }

    for (int s = 0; s < NST; s++) {
        const int j0 = jh + s * BK;

        __syncthreads();   // everyone done reading the other buffer
        if (s + 1 < NST) {
            const uint32_t nbuf = base + ((s + 1) & 1) * TILE_B;
            const int jn = j0 + BK;
#pragma unroll
            for (int q = 0; q < 4; q++) {
                const int u16 = tid + q * 512;
                const int feat = u16 >> 4, ch = u16 & 15;
                CPASYNC16(nbuf + (uint32_t)feat * ROWSTRIDE_B + ch * 16,
                          g_WhT + (size_t)feat * Nn + jn + ch * 4);
            }
        }
        CP_COMMIT();
        CP_WAIT1();        // current stage resident; next stage in flight
        __syncthreads();

        const uint32_t bb = base + (s & 1) * TILE_B + bline;

#pragma unroll
        for (int u = 0; u < 4; u++) {
            const int4 cA = nA, cB = nB;
            const float4 T0 = nT0, T1 = nT1, T2 = nT2, T3 = nT3;

            // prefetch next u (or next stage's u=0)
            if (u < 3) {
                const int ch = (j0 >> 2) + c + 4 * (u + 1);
                nA = arow0[ch]; nB = arow1[ch];
                const int jt = j0 + 4 * c + 16 * (u + 1);
                nT0 = g_tab[jt]; nT1 = g_tab[jt + 1]; nT2 = g_tab[jt + 2]; nT3 = g_tab[jt + 3];
            } else if (s + 1 < NST) {
                const int ch = ((j0 + BK) >> 2) + c;
                nA = arow0[ch]; nB = arow1[ch];
                const int jt = j0 + BK + 4 * c;
                nT0 = g_tab[jt]; nT1 = g_tab[jt + 1]; nT2 = g_tab[jt + 2]; nT3 = g_tab[jt + 3];
            }

            // produce A fragments (tf32) for ks_lo = 2u and ks_hi = 2u+1
            uint32_t Alo[4], Ahi[4];
            Alo[0] = f2tf32(Pv(cA.x, T0, thr0, cp0, cn0, lsum0));
            Alo[1] = f2tf32(Pv(cB.x, T0, thr1, cp1, cn1, lsum1));
            Alo[2] = f2tf32(Pv(cA.y, T1, thr0, cp0, cn0, lsum0));
            Alo[3] = f2tf32(Pv(cB.y, T1, thr1, cp1, cn1, lsum1));
            Ahi[0] = f2tf32(Pv(cA.z, T2, thr0, cp0, cn0, lsum0));
            Ahi[1] = f2tf32(Pv(cB.z, T2, thr1, cp1, cn1, lsum1));
            Ahi[2] = f2tf32(Pv(cA.w, T3, thr0, cp0, cn0, lsum0));
            Ahi[3] = f2tf32(Pv(cB.w, T3, thr1, cp1, cn1, lsum1));

#pragma unroll
            for (int nt = 0; nt < 8; nt++) {
                uint32_t B[4];
                LDS128(B, bb + (uint32_t)nt * (8 * ROWSTRIDE_B) + u * 64);
                mma_tf32(acc[nt], Alo, B[0], B[1]);
                mma_tf32(acc[nt], Ahi, B[2], B[3]);
            }
        }
    }

    // row-sum reduce across the 4 c-lanes of each quad
    lsum0 += __shfl_xor_sync(0xFFFFFFFFu, lsum0, 1);
    lsum0 += __shfl_xor_sync(0xFFFFFFFFu, lsum0, 2);
    lsum1 += __shfl_xor_sync(0xFFFFFFFFu, lsum1, 1);
    lsum1 += __shfl_xor_sync(0xFFFFFFFFu, lsum1, 2);
    if (wn == 0 && c == 0) {
        float* lp = half ? g_lp1 : g_lp0;
        lp[r0] = lsum0;
        lp[r1] = lsum1;
    }

    // write partial numerators (c-frag: d0/d1 row r0, d2/d3 row r1, cols 2c,2c+1)
    float* np = half ? g_np1 : g_np0;
#pragma unroll
    for (int nt = 0; nt < 8; nt++) {
        const int col = wn * 64 + nt * 8 + c * 2;
        *(float2*)(np + (size_t)r0 * OUT_F + col) = make_float2(acc[nt][0], acc[nt][1]);
        *(float2*)(np + (size_t)r1 * OUT_F + col) = make_float2(acc[nt][2], acc[nt][3]);
    }
}

// ---------------------------------------------------------------------------
// Kernel 4: combine halves, normalize
// ---------------------------------------------------------------------------
__global__ __launch_bounds__(256) void k_norm(float* __restrict__ out) {
    const int idx = blockIdx.x * 256 + threadIdx.x;  // float4 index
    const int i = idx >> 5;                          // row
    const float inv = 1.f / (g_lp0[i] + g_lp1[i]);
    const float4 x = ((const float4*)g_np0)[idx];
    const float4 y = ((const float4*)g_np1)[idx];
    ((float4*)out)[idx] = make_float4((x.x + y.x) * inv, (x.y + y.y) * inv,
                                      (x.z + y.z) * inv, (x.w + y.w) * inv);
}

// ---------------------------------------------------------------------------
extern "C" void kernel_launch(void* const* d_in, const int* in_sizes, int n_in,
                              void* d_out, int out_size) {
    const float* h   = (const float*)d_in[0];
    const int*   adj = (const int*)d_in[1];
    const float* W   = (const float*)d_in[2];
    const float* a   = (const float*)d_in[3];
    float* out = (float*)d_out;

    static int smem_set = 0;
    if (!smem_set) {
        cudaFuncSetAttribute(k_attn, cudaFuncAttributeMaxDynamicSharedMemorySize, SMEM_ATTN);
        smem_set = 1;
    }

    k_proj<<<Nn / 32, 256>>>(h, W, a);
    k_pre<<<Nn / 256, 256>>>();
    k_attn<<<(Nn / 128) * SPLIT, 512, SMEM_ATTN>>>(adj);
    k_norm<<<Nn * OUT_F / 4 / 256, 256>>>(out);
}

// round 7
// speedup vs baseline: 1.4988x; 1.2085x over previous
#include <cuda_runtime.h>
#include <cuda_fp16.h>
#include <cstdint>

#define Nn 8192
#define IN_F 256
#define OUT_F 128
#define ALPHA 0.2f
#define SPLIT 2
#define JHALF (Nn / SPLIT) /* 4096 */
#define NIT (JHALF / 16)   /* 256 k16 iterations */

// ---------------- scratch (device globals; no allocation allowed) ------------
__device__ float g_f1[Nn];
__device__ float g_f2[Nn];
__device__ float g_f2pmax[256];
__device__ __align__(16) float2 g_tab2[Nn];   // (exp(f2-fm), exp(a*(f2-fm)))
__device__ __align__(16) float4 g_rowc[Nn];   // (te, cp, cn, 0)
__device__ __align__(16) __half g_WhT_h[OUT_F * Nn];  // transposed Wh, fp16
__device__ float g_np0[Nn * OUT_F];   // partial numerators
__device__ float g_np1[Nn * OUT_F];
__device__ float g_lp0[Nn];           // partial row sums
__device__ float g_lp1[Nn];

// ---------------- helpers ----------------------------------------------------
__device__ __forceinline__ void mma_f16(float* d, const uint32_t* a, uint32_t b0, uint32_t b1) {
    asm volatile("mma.sync.aligned.m16n8k16.row.col.f32.f16.f16.f32 "
                 "{%0,%1,%2,%3},{%4,%5,%6,%7},{%8,%9},{%0,%1,%2,%3};"
                 : "+f"(d[0]), "+f"(d[1]), "+f"(d[2]), "+f"(d[3])
                 : "r"(a[0]), "r"(a[1]), "r"(a[2]), "r"(a[3]), "r"(b0), "r"(b1));
}

__device__ __forceinline__ uint32_t packh2(float hi, float lo) {
    uint32_t r;
    asm("cvt.rn.f16x2.f32 %0, %1, %2;" : "=r"(r) : "f"(hi), "f"(lo));
    return r;
}

// masked factorized-softmax numerator
__device__ __forceinline__ float pval(int a, float e2p, float e2n,
                                      float te, float cp, float cn) {
    const float e = (e2p > te) ? cp * e2p : cn * e2n;
    return (a > 0) ? e : 0.f;
}

// ---------------------------------------------------------------------------
// Kernel 1: Wh = h@W ; emits f1/f2, per-block f2 max, transposed fp16 WhT.
// ---------------------------------------------------------------------------
__global__ __launch_bounds__(256) void k_proj(const float* __restrict__ h,
                                              const float* __restrict__ W,
                                              const float* __restrict__ a) {
    __shared__ float w_s[32 * 128];
    __shared__ float h_s[32 * 33];
    __shared__ float red[32];
    const int tid = threadIdx.x;
    const int i0 = blockIdx.x * 32;
    const int row = tid >> 3;
    const int c8 = tid & 7;
    float4 acc[4];
#pragma unroll
    for (int j4 = 0; j4 < 4; j4++) acc[j4] = make_float4(0.f, 0.f, 0.f, 0.f);

    for (int kc = 0; kc < IN_F; kc += 32) {
        __syncthreads();
        const float4* wsrc = (const float4*)(W + kc * OUT_F);
#pragma unroll
        for (int u = 0; u < 4; u++) ((float4*)w_s)[tid + u * 256] = wsrc[tid + u * 256];
        {
            float4 hv = *(const float4*)(h + (size_t)(i0 + row) * IN_F + kc + c8 * 4);
            h_s[row * 33 + c8 * 4 + 0] = hv.x;
            h_s[row * 33 + c8 * 4 + 1] = hv.y;
            h_s[row * 33 + c8 * 4 + 2] = hv.z;
            h_s[row * 33 + c8 * 4 + 3] = hv.w;
        }
        __syncthreads();
#pragma unroll
        for (int kk = 0; kk < 32; kk++) {
            const float hval = h_s[row * 33 + kk];
            const float4* wr = ((const float4*)w_s) + kk * 32 + c8;
#pragma unroll
            for (int j4 = 0; j4 < 4; j4++) {
                const float4 wv = wr[j4 * 8];
                acc[j4].x = fmaf(hval, wv.x, acc[j4].x);
                acc[j4].y = fmaf(hval, wv.y, acc[j4].y);
                acc[j4].z = fmaf(hval, wv.z, acc[j4].z);
                acc[j4].w = fmaf(hval, wv.w, acc[j4].w);
            }
        }
    }

    // f1 / f2 per row (8 threads per row)
    float s1 = 0.f, s2 = 0.f;
#pragma unroll
    for (int j4 = 0; j4 < 4; j4++) {
        const float4 a1v = *(const float4*)(a + c8 * 4 + j4 * 32);
        const float4 a2v = *(const float4*)(a + OUT_F + c8 * 4 + j4 * 32);
        s1 += acc[j4].x * a1v.x + acc[j4].y * a1v.y + acc[j4].z * a1v.z + acc[j4].w * a1v.w;
        s2 += acc[j4].x * a2v.x + acc[j4].y * a2v.y + acc[j4].z * a2v.z + acc[j4].w * a2v.w;
    }
#pragma unroll
    for (int o = 1; o < 8; o <<= 1) {
        s1 += __shfl_xor_sync(0xFFFFFFFFu, s1, o);
        s2 += __shfl_xor_sync(0xFFFFFFFFu, s2, o);
    }
    if (c8 == 0) { g_f1[i0 + row] = s1; g_f2[i0 + row] = s2; red[row] = s2; }
    __syncthreads();
    if (tid < 32) {
        float m = red[tid];
#pragma unroll
        for (int o = 16; o; o >>= 1) m = fmaxf(m, __shfl_xor_sync(0xFFFFFFFFu, m, o));
        if (tid == 0) g_f2pmax[blockIdx.x] = m;
    }

    // stage Wh into w_s, then transposed fp16 write
#pragma unroll
    for (int j4 = 0; j4 < 4; j4++)
        ((float4*)w_s)[row * 32 + c8 + j4 * 8] = acc[j4];
    __syncthreads();

    const int f = tid & 127;
    const int hb = tid >> 7;   // 0: rows 0-15, 1: rows 16-31
    uint32_t pk[8];
#pragma unroll
    for (int q = 0; q < 8; q++) {
        const float v0 = w_s[(hb * 16 + 2 * q) * 128 + f];
        const float v1 = w_s[(hb * 16 + 2 * q + 1) * 128 + f];
        pk[q] = packh2(v1, v0);    // lo = v0 (even row), hi = v1
    }
    uint4* dst = (uint4*)(g_WhT_h + (size_t)f * Nn + i0 + hb * 16);
    dst[0] = make_uint4(pk[0], pk[1], pk[2], pk[3]);
    dst[1] = make_uint4(pk[4], pk[5], pk[6], pk[7]);
}

// ---------------------------------------------------------------------------
// Kernel 2: finish f2max reduction + build col/row tables. Grid 32 x 256.
// ---------------------------------------------------------------------------
__global__ __launch_bounds__(256) void k_pre() {
    __shared__ float red[256];
    const int t = threadIdx.x;
    red[t] = g_f2pmax[t];
    __syncthreads();
#pragma unroll
    for (int s = 128; s; s >>= 1) {
        if (t < s) red[t] = fmaxf(red[t], red[t + s]);
        __syncthreads();
    }
    const float fm = red[0];
    const int j = blockIdx.x * 256 + t;
    const float d = g_f2[j] - fm;
    g_tab2[j] = make_float2(expf(d), expf(ALPHA * d));
    const float f1 = g_f1[j];
    const float bound = f1 + fm;
    const float m = bound > 0.f ? bound : ALPHA * bound;
    // te: e2p_j > te  <=>  f1 + f2_j > 0
    g_rowc[j] = make_float4(expf(-f1 - fm), expf(bound - m), expf(ALPHA * bound - m), 0.f);
}

// ---------------------------------------------------------------------------
// Kernel 3: fused masked-softmax + fp16 HMMA PV GEMM. Barrier-free main loop.
// 16 warps (8 wm x 2 wn), warp tile 16 rows x 64 feats, k16 per iteration.
// A produced in registers; B fragments = direct LDG.64 from g_WhT_h
// (k<->j remap makes each (b0,b1) pair 8B contiguous); tab in 32KB smem.
// ---------------------------------------------------------------------------
__global__ __launch_bounds__(512, 1) void k_attn(const int* __restrict__ adj) {
    __shared__ float2 tab_s[JHALF];   // 32 KB

    const int tid = threadIdx.x;
    const int wid = tid >> 5, lane = tid & 31;
    const int wm = wid >> 1, wn = wid & 1;
    const int nq = lane >> 2, c = lane & 3;
    const int rb = blockIdx.x >> 1, half = blockIdx.x & 1;
    const int i0 = rb * 128, jh = half * JHALF;

    // stage the half's exp table into smem (once)
    {
        const float4* src = (const float4*)(g_tab2 + jh);
        float4* dst = (float4*)tab_s;
#pragma unroll
        for (int q = 0; q < 4; q++) dst[tid + q * 512] = src[tid + q * 512];
    }

    const int r0 = i0 + wm * 16 + nq;
    const int r1 = r0 + 8;
    const float4 rc0 = g_rowc[r0];
    const float4 rc1 = g_rowc[r1];
    const float te0 = rc0.x, cp0 = rc0.y, cn0 = rc0.z;
    const float te1 = rc1.x, cp1 = rc1.y, cn1 = rc1.z;
    const int4* arow0 = (const int4*)(adj + (size_t)r0 * Nn);
    const int4* arow1 = (const int4*)(adj + (size_t)r1 * Nn);
    const int cibase = (jh >> 2) + c;
    const __half* baseB = g_WhT_h + (size_t)(wn * 64 + nq) * Nn + jh;

    float acc[8][4];
#pragma unroll
    for (int nt = 0; nt < 8; nt++)
#pragma unroll
        for (int q = 0; q < 4; q++) acc[nt][q] = 0.f;
    float lsum0 = 0.f, lsum1 = 0.f;

    // adj prefetch ring, distance 2
    int4 pa0[2], pa1[2];
    pa0[0] = arow0[cibase];     pa1[0] = arow1[cibase];
    pa0[1] = arow0[cibase + 4]; pa1[1] = arow1[cibase + 4];

    __syncthreads();   // tab_s ready (only barrier)

#pragma unroll 2
    for (int i = 0; i < NIT; i++) {
        const int jl = 16 * i + 4 * c;
        const int4 A0 = pa0[i & 1];
        const int4 A1 = pa1[i & 1];
        if (i + 2 < NIT) {
            pa0[i & 1] = arow0[cibase + 4 * (i + 2)];
            pa1[i & 1] = arow1[cibase + 4 * (i + 2)];
        }

        const float4 tA = *(const float4*)(tab_s + jl);      // j, j+1
        const float4 tB = *(const float4*)(tab_s + jl + 2);  // j+2, j+3

        const float p00 = pval(A0.x, tA.x, tA.y, te0, cp0, cn0);
        const float p01 = pval(A0.y, tA.z, tA.w, te0, cp0, cn0);
        const float p02 = pval(A0.z, tB.x, tB.y, te0, cp0, cn0);
        const float p03 = pval(A0.w, tB.z, tB.w, te0, cp0, cn0);
        const float p10 = pval(A1.x, tA.x, tA.y, te1, cp1, cn1);
        const float p11 = pval(A1.y, tA.z, tA.w, te1, cp1, cn1);
        const float p12 = pval(A1.z, tB.x, tB.y, te1, cp1, cn1);
        const float p13 = pval(A1.w, tB.z, tB.w, te1, cp1, cn1);
        lsum0 += (p00 + p01) + (p02 + p03);
        lsum1 += (p10 + p11) + (p12 + p13);

        uint32_t Af[4];
        Af[0] = packh2(p01, p00);   // row r0, k 2c/2c+1  (j 4c,4c+1)
        Af[1] = packh2(p11, p10);   // row r1
        Af[2] = packh2(p03, p02);   // row r0, k 2c+8/+9 (j 4c+2,4c+3)
        Af[3] = packh2(p13, p12);   // row r1

        const __half* bp = baseB + jl;
#pragma unroll
        for (int nt = 0; nt < 8; nt++) {
            const uint2 bv = *(const uint2*)(bp + (size_t)nt * 8 * Nn);
            mma_f16(acc[nt], Af, bv.x, bv.y);
        }
    }

    // row-sum reduce across the 4 c-lanes of each quad
    lsum0 += __shfl_xor_sync(0xFFFFFFFFu, lsum0, 1);
    lsum0 += __shfl_xor_sync(0xFFFFFFFFu, lsum0, 2);
    lsum1 += __shfl_xor_sync(0xFFFFFFFFu, lsum1, 1);
    lsum1 += __shfl_xor_sync(0xFFFFFFFFu, lsum1, 2);
    if (wn == 0 && c == 0) {
        float* lp = half ? g_lp1 : g_lp0;
        lp[r0] = lsum0;
        lp[r1] = lsum1;
    }

    // write partial numerators (d0/d1 row r0, d2/d3 row r1, cols 2c,2c+1)
    float* np = half ? g_np1 : g_np0;
#pragma unroll
    for (int nt = 0; nt < 8; nt++) {
        const int col = wn * 64 + nt * 8 + c * 2;
        *(float2*)(np + (size_t)r0 * OUT_F + col) = make_float2(acc[nt][0], acc[nt][1]);
        *(float2*)(np + (size_t)r1 * OUT_F + col) = make_float2(acc[nt][2], acc[nt][3]);
    }
}

// ---------------------------------------------------------------------------
// Kernel 4: combine halves, normalize
// ---------------------------------------------------------------------------
__global__ __launch_bounds__(256) void k_norm(float* __restrict__ out) {
    const int idx = blockIdx.x * 256 + threadIdx.x;  // float4 index
    const int i = idx >> 5;                          // row
    const float inv = 1.f / (g_lp0[i] + g_lp1[i]);
    const float4 x = ((const float4*)g_np0)[idx];
    const float4 y = ((const float4*)g_np1)[idx];
    ((float4*)out)[idx] = make_float4((x.x + y.x) * inv, (x.y + y.y) * inv,
                                      (x.z + y.z) * inv, (x.w + y.w) * inv);
}

// ---------------------------------------------------------------------------
extern "C" void kernel_launch(void* const* d_in, const int* in_sizes, int n_in,
                              void* d_out, int out_size) {
    const float* h   = (const float*)d_in[0];
    const int*   adj = (const int*)d_in[1];
    const float* W   = (const float*)d_in[2];
    const float* a   = (const float*)d_in[3];
    float* out = (float*)d_out;

    k_proj<<<Nn / 32, 256>>>(h, W, a);
    k_pre<<<Nn / 256, 256>>>();
    k_attn<<<(Nn / 128) * SPLIT, 512>>>(adj);
    k_norm<<<Nn * OUT_F / 4 / 256, 256>>>(out);
}

// round 8
// speedup vs baseline: 2.0106x; 1.3415x over previous
#include <cuda_runtime.h>
#include <cuda_fp16.h>
#include <cstdint>

#define Nn 8192
#define IN_F 256
#define OUT_F 128
#define ALPHA 0.2f
#define SPLIT 2
#define JHALF (Nn / SPLIT) /* 4096 */
#define NIT (JHALF / 16)   /* 256 k16 iterations */

// ---------------- scratch (device globals; no allocation allowed) ------------
__device__ float g_f1[Nn];
__device__ float g_f2[Nn];
__device__ float g_f2pmax[256];
__device__ __align__(16) float2 g_tab2[Nn];   // (exp(f2-fm), exp(a*(f2-fm)))
__device__ __align__(16) float4 g_rowc[Nn];   // (te, cp, cn, 0)
// Wh in fp16, MMA-fragment-major: uint2 index = ((jblk*2 + wn)*8 + nt)*32 + lane
//   lane = nq*4 + c ; .x = half2(Wh[j],Wh[j+1]), .y = half2(Wh[j+2],Wh[j+3]),
//   j = jblk*16 + 4c, feat = wn*64 + nt*8 + nq
__device__ __align__(16) uint2 g_Bf[(Nn / 16) * 2 * 8 * 32];
__device__ float g_np0[Nn * OUT_F];   // partial numerators
__device__ float g_np1[Nn * OUT_F];
__device__ float g_lp0[Nn];           // partial row sums
__device__ float g_lp1[Nn];

// ---------------- helpers ----------------------------------------------------
__device__ __forceinline__ void mma_f16(float* d, const uint32_t* a, uint32_t b0, uint32_t b1) {
    asm volatile("mma.sync.aligned.m16n8k16.row.col.f32.f16.f16.f32 "
                 "{%0,%1,%2,%3},{%4,%5,%6,%7},{%8,%9},{%0,%1,%2,%3};"
                 : "+f"(d[0]), "+f"(d[1]), "+f"(d[2]), "+f"(d[3])
                 : "r"(a[0]), "r"(a[1]), "r"(a[2]), "r"(a[3]), "r"(b0), "r"(b1));
}

__device__ __forceinline__ uint32_t packh2(float hi, float lo) {
    uint32_t r;
    asm("cvt.rn.f16x2.f32 %0, %1, %2;" : "=r"(r) : "f"(hi), "f"(lo));
    return r;
}

// masked factorized-softmax numerator
__device__ __forceinline__ float pval(int a, float e2p, float e2n,
                                      float te, float cp, float cn) {
    const float e = (e2p > te) ? cp * e2p : cn * e2n;
    return (a > 0) ? e : 0.f;
}

// ---------------------------------------------------------------------------
// Kernel 1: Wh = h@W ; emits f1/f2, per-block f2 max, fragment-major fp16 Bf.
// ---------------------------------------------------------------------------
__global__ __launch_bounds__(256) void k_proj(const float* __restrict__ h,
                                              const float* __restrict__ W,
                                              const float* __restrict__ a) {
    __shared__ float w_s[32 * 128];
    __shared__ float h_s[32 * 33];
    __shared__ float red[32];
    const int tid = threadIdx.x;
    const int i0 = blockIdx.x * 32;
    const int row = tid >> 3;
    const int c8 = tid & 7;
    float4 acc[4];
#pragma unroll
    for (int j4 = 0; j4 < 4; j4++) acc[j4] = make_float4(0.f, 0.f, 0.f, 0.f);

    for (int kc = 0; kc < IN_F; kc += 32) {
        __syncthreads();
        const float4* wsrc = (const float4*)(W + kc * OUT_F);
#pragma unroll
        for (int u = 0; u < 4; u++) ((float4*)w_s)[tid + u * 256] = wsrc[tid + u * 256];
        {
            float4 hv = *(const float4*)(h + (size_t)(i0 + row) * IN_F + kc + c8 * 4);
            h_s[row * 33 + c8 * 4 + 0] = hv.x;
            h_s[row * 33 + c8 * 4 + 1] = hv.y;
            h_s[row * 33 + c8 * 4 + 2] = hv.z;
            h_s[row * 33 + c8 * 4 + 3] = hv.w;
        }
        __syncthreads();
#pragma unroll
        for (int kk = 0; kk < 32; kk++) {
            const float hval = h_s[row * 33 + kk];
            const float4* wr = ((const float4*)w_s) + kk * 32 + c8;
#pragma unroll
            for (int j4 = 0; j4 < 4; j4++) {
                const float4 wv = wr[j4 * 8];
                acc[j4].x = fmaf(hval, wv.x, acc[j4].x);
                acc[j4].y = fmaf(hval, wv.y, acc[j4].y);
                acc[j4].z = fmaf(hval, wv.z, acc[j4].z);
                acc[j4].w = fmaf(hval, wv.w, acc[j4].w);
            }
        }
    }

    // f1 / f2 per row (8 threads per row)
    float s1 = 0.f, s2 = 0.f;
#pragma unroll
    for (int j4 = 0; j4 < 4; j4++) {
        const float4 a1v = *(const float4*)(a + c8 * 4 + j4 * 32);
        const float4 a2v = *(const float4*)(a + OUT_F + c8 * 4 + j4 * 32);
        s1 += acc[j4].x * a1v.x + acc[j4].y * a1v.y + acc[j4].z * a1v.z + acc[j4].w * a1v.w;
        s2 += acc[j4].x * a2v.x + acc[j4].y * a2v.y + acc[j4].z * a2v.z + acc[j4].w * a2v.w;
    }
#pragma unroll
    for (int o = 1; o < 8; o <<= 1) {
        s1 += __shfl_xor_sync(0xFFFFFFFFu, s1, o);
        s2 += __shfl_xor_sync(0xFFFFFFFFu, s2, o);
    }
    if (c8 == 0) { g_f1[i0 + row] = s1; g_f2[i0 + row] = s2; red[row] = s2; }
    __syncthreads();
    if (tid < 32) {
        float m = red[tid];
#pragma unroll
        for (int o = 16; o; o >>= 1) m = fmaxf(m, __shfl_xor_sync(0xFFFFFFFFu, m, o));
        if (tid == 0) g_f2pmax[blockIdx.x] = m;
    }

    // stage Wh into w_s, then fragment-major fp16 write
#pragma unroll
    for (int j4 = 0; j4 < 4; j4++)
        ((float4*)w_s)[row * 32 + c8 + j4 * 8] = acc[j4];
    __syncthreads();

    const int f = tid & 127;
    const int hb = tid >> 7;   // 0: block rows 0-15, 1: rows 16-31
    const int wn = f >> 6, nt = (f >> 3) & 7, nq = f & 7;
    uint32_t* bf32 = (uint32_t*)g_Bf;
#pragma unroll
    for (int q = 0; q < 8; q++) {
        const int jj = hb * 16 + 2 * q;            // local row (even)
        const float v0 = w_s[jj * 128 + f];
        const float v1 = w_s[(jj + 1) * 128 + f];
        const uint32_t pk = packh2(v1, v0);        // lo = j, hi = j+1
        const int jblk = (i0 + jj) >> 4;
        const int c = (jj >> 2) & 3;
        const int v = jj & 3;                      // 0 or 2
        const int widx = ((((jblk * 2 + wn) * 8 + nt) * 32) + nq * 4 + c) * 2 + (v >> 1);
        bf32[widx] = pk;
    }
}

// ---------------------------------------------------------------------------
// Kernel 2: finish f2max reduction + build col/row tables. Grid 32 x 256.
// ---------------------------------------------------------------------------
__global__ __launch_bounds__(256) void k_pre() {
    __shared__ float red[256];
    const int t = threadIdx.x;
    red[t] = g_f2pmax[t];
    __syncthreads();
#pragma unroll
    for (int s = 128; s; s >>= 1) {
        if (t < s) red[t] = fmaxf(red[t], red[t + s]);
        __syncthreads();
    }
    const float fm = red[0];
    const int j = blockIdx.x * 256 + t;
    const float d = g_f2[j] - fm;
    g_tab2[j] = make_float2(expf(d), expf(ALPHA * d));
    const float f1 = g_f1[j];
    const float bound = f1 + fm;
    const float m = bound > 0.f ? bound : ALPHA * bound;
    g_rowc[j] = make_float4(expf(-f1 - fm), expf(bound - m), expf(ALPHA * bound - m), 0.f);
}

// ---------------------------------------------------------------------------
// Kernel 3: fused masked-softmax + fp16 HMMA PV GEMM. Barrier-free main loop.
// B fragments: single coalesced LDG.64 per n-tile (2 L1 wavefronts each).
// ---------------------------------------------------------------------------
__global__ __launch_bounds__(512, 1) void k_attn(const int* __restrict__ adj) {
    __shared__ float2 tab_s[JHALF];   // 32 KB

    const int tid = threadIdx.x;
    const int wid = tid >> 5, lane = tid & 31;
    const int wm = wid >> 1, wn = wid & 1;
    const int nq = lane >> 2, c = lane & 3;
    const int rb = blockIdx.x >> 1, half = blockIdx.x & 1;
    const int i0 = rb * 128, jh = half * JHALF;

    // stage the half's exp table into smem (once)
    {
        const float4* src = (const float4*)(g_tab2 + jh);
        float4* dst = (float4*)tab_s;
#pragma unroll
        for (int q = 0; q < 4; q++) dst[tid + q * 512] = src[tid + q * 512];
    }

    const int r0 = i0 + wm * 16 + nq;
    const int r1 = r0 + 8;
    const float4 rc0 = g_rowc[r0];
    const float4 rc1 = g_rowc[r1];
    const float te0 = rc0.x, cp0 = rc0.y, cn0 = rc0.z;
    const float te1 = rc1.x, cp1 = rc1.y, cn1 = rc1.z;
    const int4* arow0 = (const int4*)(adj + (size_t)r0 * Nn);
    const int4* arow1 = (const int4*)(adj + (size_t)r1 * Nn);
    const int cibase = (jh >> 2) + c;
    const uint2* bfbase = g_Bf + ((size_t)(jh >> 4) * 2 + wn) * 256 + lane;

    float acc[8][4];
#pragma unroll
    for (int nt = 0; nt < 8; nt++)
#pragma unroll
        for (int q = 0; q < 4; q++) acc[nt][q] = 0.f;
    float lsum0 = 0.f, lsum1 = 0.f;

    // adj prefetch ring, distance 2
    int4 pa0[2], pa1[2];
    pa0[0] = arow0[cibase];     pa1[0] = arow1[cibase];
    pa0[1] = arow0[cibase + 4]; pa1[1] = arow1[cibase + 4];

    // B prefetch: iteration 0
    uint2 bv[8];
#pragma unroll
    for (int nt = 0; nt < 8; nt++) bv[nt] = bfbase[nt * 32];

    __syncthreads();   // tab_s ready (only barrier)

#pragma unroll 2
    for (int i = 0; i < NIT; i++) {
        const int jl = 16 * i + 4 * c;
        const int4 A0 = pa0[i & 1];
        const int4 A1 = pa1[i & 1];
        if (i + 2 < NIT) {
            pa0[i & 1] = arow0[cibase + 4 * (i + 2)];
            pa1[i & 1] = arow1[cibase + 4 * (i + 2)];
        }

        // prefetch next iteration's B fragments (last iter reloads itself)
        const uint2* bq = bfbase + (size_t)(i + 1 < NIT ? i + 1 : i) * 512;
        uint2 nbv[8];
#pragma unroll
        for (int nt = 0; nt < 8; nt++) nbv[nt] = bq[nt * 32];

        const float4 tA = *(const float4*)(tab_s + jl);      // j, j+1
        const float4 tB = *(const float4*)(tab_s + jl + 2);  // j+2, j+3

        const float p00 = pval(A0.x, tA.x, tA.y, te0, cp0, cn0);
        const float p01 = pval(A0.y, tA.z, tA.w, te0, cp0, cn0);
        const float p02 = pval(A0.z, tB.x, tB.y, te0, cp0, cn0);
        const float p03 = pval(A0.w, tB.z, tB.w, te0, cp0, cn0);
        const float p10 = pval(A1.x, tA.x, tA.y, te1, cp1, cn1);
        const float p11 = pval(A1.y, tA.z, tA.w, te1, cp1, cn1);
        const float p12 = pval(A1.z, tB.x, tB.y, te1, cp1, cn1);
        const float p13 = pval(A1.w, tB.z, tB.w, te1, cp1, cn1);
        lsum0 += (p00 + p01) + (p02 + p03);
        lsum1 += (p10 + p11) + (p12 + p13);

        uint32_t Af[4];
        Af[0] = packh2(p01, p00);   // row r0, k 2c/2c+1  (j 4c,4c+1)
        Af[1] = packh2(p11, p10);   // row r1
        Af[2] = packh2(p03, p02);   // row r0, k 2c+8/+9 (j 4c+2,4c+3)
        Af[3] = packh2(p13, p12);   // row r1

#pragma unroll
        for (int nt = 0; nt < 8; nt++)
            mma_f16(acc[nt], Af, bv[nt].x, bv[nt].y);

#pragma unroll
        for (int nt = 0; nt < 8; nt++) bv[nt] = nbv[nt];
    }

    // row-sum reduce across the 4 c-lanes of each quad
    lsum0 += __shfl_xor_sync(0xFFFFFFFFu, lsum0, 1);
    lsum0 += __shfl_xor_sync(0xFFFFFFFFu, lsum0, 2);
    lsum1 += __shfl_xor_sync(0xFFFFFFFFu, lsum1, 1);
    lsum1 += __shfl_xor_sync(0xFFFFFFFFu, lsum1, 2);
    if (wn == 0 && c == 0) {
        float* lp = half ? g_lp1 : g_lp0;
        lp[r0] = lsum0;
        lp[r1] = lsum1;
    }

    // write partial numerators (d0/d1 row r0, d2/d3 row r1, cols 2c,2c+1)
    float* np = half ? g_np1 : g_np0;
#pragma unroll
    for (int nt = 0; nt < 8; nt++) {
        const int col = wn * 64 + nt * 8 + c * 2;
        *(float2*)(np + (size_t)r0 * OUT_F + col) = make_float2(acc[nt][0], acc[nt][1]);
        *(float2*)(np + (size_t)r1 * OUT_F + col) = make_float2(acc[nt][2], acc[nt][3]);
    }
}

// ---------------------------------------------------------------------------
// Kernel 4: combine halves, normalize
// ---------------------------------------------------------------------------
__global__ __launch_bounds__(256) void k_norm(float* __restrict__ out) {
    const int idx = blockIdx.x * 256 + threadIdx.x;  // float4 index
    const int i = idx >> 5;                          // row
    const float inv = 1.f / (g_lp0[i] + g_lp1[i]);
    const float4 x = ((const float4*)g_np0)[idx];
    const float4 y = ((const float4*)g_np1)[idx];
    ((float4*)out)[idx] = make_float4((x.x + y.x) * inv, (x.y + y.y) * inv,
                                      (x.z + y.z) * inv, (x.w + y.w) * inv);
}

// ---------------------------------------------------------------------------
extern "C" void kernel_launch(void* const* d_in, const int* in_sizes, int n_in,
                              void* d_out, int out_size) {
    const float* h   = (const float*)d_in[0];
    const int*   adj = (const int*)d_in[1];
    const float* W   = (const float*)d_in[2];
    const float* a   = (const float*)d_in[3];
    float* out = (float*)d_out;

    k_proj<<<Nn / 32, 256>>>(h, W, a);
    k_pre<<<Nn / 256, 256>>>();
    k_attn<<<(Nn / 128) * SPLIT, 512>>>(adj);
    k_norm<<<Nn * OUT_F / 4 / 256, 256>>>(out);
}